// round 5
// baseline (speedup 1.0000x reference)
#include <cuda_runtime.h>

#define T_STEPS 20

typedef unsigned long long u64;

__device__ __forceinline__ u64 pack2(float x, float y) {
    u64 r; asm("mov.b64 %0, {%1, %2};" : "=l"(r) : "f"(x), "f"(y)); return r;
}
__device__ __forceinline__ void unpack2(u64 v, float& x, float& y) {
    asm("mov.b64 {%0, %1}, %2;" : "=f"(x), "=f"(y) : "l"(v));
}
// Packed fma: each half is an independent fma.rn.f32 -> bit-identical to scalar FFMA.
__device__ __forceinline__ u64 ffma2(u64 a, u64 b, u64 c) {
    u64 d; asm("fma.rn.f32x2 %0, %1, %2, %3;" : "=l"(d) : "l"(a), "l"(b), "l"(c)); return d;
}
__device__ __forceinline__ u64 fmul2(u64 a, u64 b) {
    u64 d; asm("mul.rn.f32x2 %0, %1, %2;" : "=l"(d) : "l"(a), "l"(b)); return d;
}
// FSET: float 1.0f/0.0f result of (a > b) in ONE instruction.
__device__ __forceinline__ float fset_gt(float a, float b) {
    float d; asm("set.gt.f32.f32 %0, %1, %2;" : "=f"(d) : "f"(a), "f"(b)); return d;
}

__global__ void __launch_bounds__(256) xornet_snn_kernel(
    const float4* __restrict__ x4,   // x [B,2]: one float4 = 2 batch elems
    const float*  __restrict__ w1,   // [4,2]
    const float*  __restrict__ w2,   // [1,4]
    float*        __restrict__ out,  // [T, B]
    int B)
{
    const int i  = blockIdx.x * blockDim.x + threadIdx.x;  // pair of batch elems
    const int b0 = i * 2;
    if (b0 >= B) return;

    // 2 batch elems per thread: one float4 load
    const float4 xa = x4[i];          // b0:{x0,x1}, b1:{x0,x1}
    const float px0[2] = {xa.x, xa.z};
    const float px1[2] = {xa.y, xa.w};

    float w1v[4][2];
#pragma unroll
    for (int h = 0; h < 4; h++) {
        w1v[h][0] = __ldg(&w1[2 * h + 0]);
        w1v[h][1] = __ldg(&w1[2 * h + 1]);
    }
    u64 W2[4];
#pragma unroll
    for (int h = 0; h < 4; h++) {
        float w = __ldg(&w2[h]);
        W2[h] = pack2(w, w);
    }

    // cur[h]: packed pair of lanes; same fma chain as before (bit-identical).
    u64 cur[4];
#pragma unroll
    for (int h = 0; h < 4; h++) {
        float c0 = fmaf(px1[0], w1v[h][1], px0[0] * w1v[h][0]);
        float c1 = fmaf(px1[1], w1v[h][1], px0[1] * w1v[h][0]);
        cur[h] = pack2(c0, c1);
    }

    const u64 BETA2 = pack2(0.9f, 0.9f);
    const u64 NEG1  = pack2(-1.0f, -1.0f);
    const u64 ZERO2 = pack2(0.0f, 0.0f);

    // Packed membranes + previous spikes (prev spike == this step's reset;
    // (m-1>0) <=> (m>1) exactly in fp32).
    u64 m1[4], s1[4];
#pragma unroll
    for (int h = 0; h < 4; h++) { m1[h] = ZERO2; s1[h] = ZERO2; }
    u64 m2 = ZERO2, s2 = ZERO2;

    float* outp = out + b0;

#pragma unroll
    for (int t = 0; t < T_STEPS; t++) {
#pragma unroll
        for (int h = 0; h < 4; h++) {
            // m = beta*m + cur  (packed fma, bit-identical halves)
            u64 m = ffma2(BETA2, m1[h], cur[h]);
            // m -= s_prev : fma(s,-1,m) == m-1 (single rounding, == FADD) or m exactly
            m = ffma2(s1[h], NEG1, m);
            m1[h] = m;
            float lo, hi; unpack2(m, lo, hi);
            s1[h] = pack2(fset_gt(lo, 1.0f), fset_gt(hi, 1.0f));
        }
        // o = spk1 . w2 : packed mul + fma chain, same h-order & values as scalar chain
        u64 o = fmul2(s1[0], W2[0]);
        o = ffma2(s1[1], W2[1], o);
        o = ffma2(s1[2], W2[2], o);
        o = ffma2(s1[3], W2[3], o);

        u64 m = ffma2(BETA2, m2, o);
        m = ffma2(s2, NEG1, m);
        m2 = m;
        float lo, hi; unpack2(m, lo, hi);
        float so0 = fset_gt(lo, 1.0f);
        float so1 = fset_gt(hi, 1.0f);
        s2 = pack2(so0, so1);

        *reinterpret_cast<float2*>(outp) = make_float2(so0, so1);
        outp += B;  // next timestep plane
    }
}

extern "C" void kernel_launch(void* const* d_in, const int* in_sizes, int n_in,
                              void* d_out, int out_size)
{
    const float* x  = (const float*)d_in[0];   // [B, 2]
    const float* w1 = (const float*)d_in[1];   // [4, 2]
    const float* w2 = (const float*)d_in[2];   // [1, 4]
    float* out      = (float*)d_out;           // [T, B, 1]

    const int B = in_sizes[0] / 2;
    const int nthreads = B / 2;                // 2 batch elems per thread
    const int block = 256;
    const int grid = (nthreads + block - 1) / block;

    xornet_snn_kernel<<<grid, block>>>((const float4*)x, w1, w2, out, B);
}